// round 9
// baseline (speedup 1.0000x reference)
#include <cuda_runtime.h>

#define BATCH 131072
#define NCH 16
#define NK 15
#define NZ 256
#define NCOUT 10
#define MAXREG 128
#define VOCAB 1024
#define ZPAD 260                  // smem row stride (floats): 4-bank skew per row, 16B aligned

typedef unsigned long long u64;

// ---------------- scratch (device globals; no allocation) ----------------
__device__ unsigned       g_seen[NCH][1024];     // built by k_masks, read+zeroed by k_tables
__device__ unsigned char  g_rmap[NCH][32768];    // mask -> region id (observed entries valid this launch)
__device__ unsigned       g_maskw[BATCH * 8];    // packed masks: channel pair per u32
__device__ int            g_cnt[NCH];            // #distinct masks per channel (<=121)
__device__ float          g_zreg[NCH][MAXREG][NZ];       // per-region half z-row
__device__ unsigned char  g_cross[8][MAXREG][MAXREG];    // argmax index per (c8, rA, rB)

// ================= K1: per-element sign masks (f32x2 packed planes, fused observation) ===
#define K1_BLK 256
#define K1_THR 512
#define K1_SMEM (8192 + 8192 + 2880 + 65536)   // 84800 B

__global__ void __launch_bounds__(K1_THR, 2) k_masks(
    const int* __restrict__ x, const float* __restrict__ lenLUT,
    const float* __restrict__ ipdLUT, const float* __restrict__ S,
    const float* __restrict__ T)
{
    extern __shared__ char dyn[];
    float2*   sLen = (float2*)dyn;                       // 8 KB
    float2*   sIpd = (float2*)(dyn + 8192);              // 8 KB
    u64*      sS0  = (u64*)(dyn + 16384);                // 8 pairs x 15 k, packed (cA,cB)
    u64*      sS1  = sS0 + 120;
    u64*      sC   = sS1 + 120;                          // packed (-T-1e-4)
    unsigned* filt = (unsigned*)(dyn + 16384 + 2880);    // 64 KB block-local seen filter

    const int tid = threadIdx.x;
    for (int i = tid; i < VOCAB; i += K1_THR) {
        sLen[i] = ((const float2*)lenLUT)[i];
        sIpd[i] = ((const float2*)ipdLUT)[i];
    }
    if (tid < 120) {                                     // pack per-pair plane constants
        int i = tid / NK, k = tid % NK;
        int cA = 2 * i, cB = 2 * i + 1;
        u64 s0 = ((u64)__float_as_uint(S[cB * 30 + k])      << 32) | __float_as_uint(S[cA * 30 + k]);
        u64 s1 = ((u64)__float_as_uint(S[cB * 30 + 15 + k]) << 32) | __float_as_uint(S[cA * 30 + 15 + k]);
        float cAv = -T[cA * NK + k] - 1e-4f;
        float cBv = -T[cB * NK + k] - 1e-4f;
        u64 cc = ((u64)__float_as_uint(cBv) << 32) | __float_as_uint(cAv);
        sS0[tid] = s0; sS1[tid] = s1; sC[tid] = cc;
    }
    for (int i = tid; i < NCH * 1024; i += K1_THR) filt[i] = 0u;
    __syncthreads();

    const int b = blockIdx.x * K1_THR + tid;             // exact cover: 256*512 = BATCH
    const int4* xp = (const int4*)x + (size_t)b * 8;

    unsigned words[8];
    #pragma unroll
    for (int i = 0; i < 8; i++) {
        int4   xv = __ldg(&xp[i]);
        float2 lA = sLen[xv.x], pA = sIpd[xv.y];
        float2 lB = sLen[xv.z], pB = sIpd[xv.w];
        float e0A = lA.x + pA.x, e1A = lA.y + pA.y;
        float e0B = lB.x + pB.x, e1B = lB.y + pB.y;
        u64 e0p, e1p;
        asm("mov.b64 %0, {%1, %2};" : "=l"(e0p) : "f"(e0A), "f"(e0B));
        asm("mov.b64 %0, {%1, %2};" : "=l"(e1p) : "f"(e1A), "f"(e1B));
        unsigned pair = 0;
        #pragma unroll
        for (int k = 0; k < NK; k++) {
            u64 t2, y2;
            asm("fma.rn.f32x2 %0, %1, %2, %3;" : "=l"(t2) : "l"(e0p), "l"(sS0[i * NK + k]), "l"(sC[i * NK + k]));
            asm("fma.rn.f32x2 %0, %1, %2, %3;" : "=l"(y2) : "l"(e1p), "l"(sS1[i * NK + k]), "l"(t2));
            unsigned lo = (unsigned)y2;
            unsigned hi = (unsigned)(y2 >> 32);
            pair |= ((lo >> 31) << k) | ((hi >> 31) << (16 + k));   // bit set <=> y<0
        }
        words[i] = pair;
    }

    uint4* mp = (uint4*)&g_maskw[(size_t)b * 8];
    mp[0] = make_uint4(words[0], words[1], words[2], words[3]);
    mp[1] = make_uint4(words[4], words[5], words[6], words[7]);

    // seen-set update pass (block filter -> rare global atomic)
    #pragma unroll
    for (int i = 0; i < 8; i++) {
        #pragma unroll
        for (int h = 0; h < 2; h++) {
            unsigned m = (words[i] >> (16 * h)) & 0xffffu;
            int c = 2 * i + h;
            unsigned word = c * 1024 + (m >> 5), bit = 1u << (m & 31);
            if (!(filt[word] & bit)) {
                unsigned old = atomicOr(&filt[word], bit);
                if (!(old & bit)) atomicOr(&g_seen[c][m >> 5], bit);
            }
        }
    }
}

// ================= K2: dedup + global region map + self-clean + zreg =================
__global__ void __launch_bounds__(1024) k_tables(const float* __restrict__ H) {  // <<<16, 1024>>>
    const int c = blockIdx.x, tid = threadIdx.x;
    __shared__ int            sc[256];
    __shared__ unsigned short sMask[MAXREG];
    __shared__ float          sH[NK][NZ];
    __shared__ int            s_cnt;

    unsigned w[4]; int pc = 0;
    if (tid < 256) {
        #pragma unroll
        for (int j = 0; j < 4; j++) {
            w[j] = g_seen[c][tid * 4 + j];
            g_seen[c][tid * 4 + j] = 0u;               // self-clean for next launch
            pc += __popc(w[j]);
        }
        sc[tid] = pc;
    }
    const int base = (c & 1) * NK;                     // even ch -> H rows 0..14, odd -> 15..29
    for (int i = tid; i < NK * NZ; i += 1024)
        sH[i >> 8][i & 255] = H[(base + (i >> 8)) * NZ + (i & 255)];
    __syncthreads();
    for (int off = 1; off < 256; off <<= 1) {          // Hillis-Steele inclusive scan (256 lanes)
        int v = 0;
        if (tid < 256 && tid >= off) v = sc[tid - off];
        __syncthreads();
        if (tid < 256) sc[tid] += v;
        __syncthreads();
    }
    if (tid < 256) {
        int id = sc[tid] - pc;                         // exclusive prefix (ascending-mask order)
        if (tid == 255) { g_cnt[c] = min(sc[255], MAXREG); s_cnt = min(sc[255], MAXREG); }
        #pragma unroll
        for (int j = 0; j < 4; j++) {
            const int word = tid * 4 + j;
            unsigned ww = w[j];
            const unsigned mb = (unsigned)word << 5;
            while (ww) {
                int bb = __ffs(ww) - 1; ww &= ww - 1;
                if (id < MAXREG) {
                    unsigned short mask = (unsigned short)(mb | (unsigned)bb);
                    g_rmap[c][mask] = (unsigned char)id;   // global mask -> region id
                    sMask[id] = mask;
                }
                id++;
            }
        }
    }
    __syncthreads();

    const int cnt = s_cnt;
    const int col = tid & 255, grp = tid >> 8;         // 4-way row parallelism
    for (int r = grp; r < cnt; r += 4) {
        unsigned m = sMask[r];
        float acc = 0.f;
        #pragma unroll
        for (int d = 0; d < NK; d++) {
            float hv = sH[d][col];
            acc += ((m >> d) & 1) ? -hv : hv;
        }
        g_zreg[c][r][col] = acc;
    }
}

// ================= K3: argmax table — one thread per (rA,rB) pair, no shuffles =========
// grid = dim3(4 rA-tiles, 4 rB-tiles, 8 pairs), block = 256 (8 warps).
// lane <-> rA within 32-row tile (zA staged in smem, 260-float stride: conflict-free LDS.128);
// warp <-> rB (zB row via broadcast __ldg float4). Serial ascending-k chain keeps
// first-index-wins semantics; two rB chains interleaved for ILP.
#define KX_SMEM (32 * ZPAD * 4)   // 33280 B

__global__ void __launch_bounds__(256) k_cross() {
    const int rAt = blockIdx.x, rBt = blockIdx.y, c8 = blockIdx.z;
    const int cA = 2 * c8, cB = cA + 1;
    const int nA = g_cnt[cA], nB = g_cnt[cB];
    const int rA0 = rAt * 32, rB0 = rBt * 32;
    if (rA0 >= nA || rB0 >= nB) return;                 // uniform per block

    extern __shared__ float zA[];                       // [32][ZPAD]
    const int tid = threadIdx.x;
    for (int i = tid; i < 32 * NZ; i += 256) {          // stage zA tile (rows beyond nA unused)
        int row = i >> 8, col = i & 255;
        zA[row * ZPAD + col] = g_zreg[cA][rA0 + row][col];
    }
    __syncthreads();

    const int warp = tid >> 5, lane = tid & 31;
    const int rA = rA0 + lane;
    const bool aLive = (rA < nA);
    const float4* zAl = (const float4*)&zA[lane * ZPAD];
    const int nBt = min(32, nB - rB0);                  // live rB rows in this tile

    for (int rb = warp; rb < nBt; rb += 16) {           // two chains interleaved (rb, rb+8)
        const int rB_0 = rB0 + rb;
        const int rB_1 = rB0 + rb + 8;
        const bool live1 = (rb + 8 < nBt);
        const float4* zb0 = (const float4*)&g_zreg[cB][rB_0][0];
        const float4* zb1 = (const float4*)&g_zreg[cB][live1 ? rB_1 : rB_0][0];

        float best0 = __int_as_float(0xff800000), best1 = best0;   // -inf
        int   bk0 = 0, bk1 = 0;
        #pragma unroll 4
        for (int k4 = 0; k4 < 64; k4++) {
            float4 a  = zAl[k4];
            float4 b0 = __ldg(&zb0[k4]);
            float4 b1 = __ldg(&zb1[k4]);
            int kb = k4 * 4;
            float v;
            v = a.x + b0.x; if (v > best0) { best0 = v; bk0 = kb;     }
            v = a.y + b0.y; if (v > best0) { best0 = v; bk0 = kb + 1; }
            v = a.z + b0.z; if (v > best0) { best0 = v; bk0 = kb + 2; }
            v = a.w + b0.w; if (v > best0) { best0 = v; bk0 = kb + 3; }
            v = a.x + b1.x; if (v > best1) { best1 = v; bk1 = kb;     }
            v = a.y + b1.y; if (v > best1) { best1 = v; bk1 = kb + 1; }
            v = a.z + b1.z; if (v > best1) { best1 = v; bk1 = kb + 2; }
            v = a.w + b1.w; if (v > best1) { best1 = v; bk1 = kb + 3; }
        }
        if (aLive) {
            g_cross[c8][rA][rB_0] = (unsigned char)bk0;
            if (live1) g_cross[c8][rA][rB_1] = (unsigned char)bk1;
        }
    }
}

// ================= K4: gather (L2 rmap/cross + smem LUT) + log_softmax =================
#define K4_BLK 256
#define K4_THR 512
#define LUTPAD 12
#define K4_SMEM (8 * 256 * LUTPAD * 4)   // 98304 B -> 2 blocks/SM

__global__ void __launch_bounds__(K4_THR, 2) k_main(
    const float* __restrict__ LUT, float* __restrict__ out)
{
    extern __shared__ char dyn[];
    float* slut = (float*)dyn;

    const int tid = threadIdx.x;
    for (int row = tid; row < 8 * 256; row += K4_THR) {
        #pragma unroll
        for (int j = 0; j < LUTPAD; j++)
            slut[row * LUTPAD + j] = (j < NCOUT) ? LUT[row * NCOUT + j] : 0.f;
    }
    __syncthreads();

    const int b = blockIdx.x * K4_THR + tid;             // exact cover: 256*512 = BATCH
    const uint4* mp = (const uint4*)&g_maskw[(size_t)b * 8];
    uint4 m0 = mp[0], m1 = mp[1];
    unsigned mw[8] = {m0.x, m0.y, m0.z, m0.w, m1.x, m1.y, m1.z, m1.w};

    int r[NCH];
    #pragma unroll
    for (int i = 0; i < 8; i++) {                        // 16 independent L2 u8 loads
        r[2 * i]     = __ldg(&g_rmap[2 * i][mw[i] & 0xffffu]);
        r[2 * i + 1] = __ldg(&g_rmap[2 * i + 1][mw[i] >> 16]);
    }

    int idx[8];
    #pragma unroll
    for (int c8 = 0; c8 < 8; c8++)                       // 8 independent L2 u8 loads
        idx[c8] = __ldg(&g_cross[c8][r[2 * c8]][r[2 * c8 + 1]]);

    float4 a0 = make_float4(0.f, 0.f, 0.f, 0.f), a1 = a0, a2 = a0;
    #pragma unroll
    for (int c8 = 0; c8 < 8; c8++) {
        const float4* p = (const float4*)&slut[(c8 * 256 + idx[c8]) * LUTPAD];
        float4 v0 = p[0], v1 = p[1], v2 = p[2];
        a0.x += v0.x; a0.y += v0.y; a0.z += v0.z; a0.w += v0.w;
        a1.x += v1.x; a1.y += v1.y; a1.z += v1.z; a1.w += v1.w;
        a2.x += v2.x; a2.y += v2.y;                      // lanes 10,11 are pad
    }
    float acc[NCOUT] = {a0.x, a0.y, a0.z, a0.w, a1.x, a1.y, a1.z, a1.w, a2.x, a2.y};

    float mx = acc[0];
    #pragma unroll
    for (int j = 1; j < NCOUT; j++) mx = fmaxf(mx, acc[j]);
    float s = 0.f;
    #pragma unroll
    for (int j = 0; j < NCOUT; j++) s += __expf(acc[j] - mx);
    float lg = __logf(s);

    float2* op = (float2*)(out + (size_t)b * NCOUT);
    #pragma unroll
    for (int j = 0; j < 5; j++)
        op[j] = make_float2((acc[2 * j] - mx) - lg, (acc[2 * j + 1] - mx) - lg);
}

// ---------------- launch ----------------
extern "C" void kernel_launch(void* const* d_in, const int* in_sizes, int n_in,
                              void* d_out, int out_size) {
    const int*   x      = (const int*)d_in[0];
    const float* lenLUT = (const float*)d_in[1];
    const float* ipdLUT = (const float*)d_in[2];
    const float* S      = (const float*)d_in[3];
    const float* H      = (const float*)d_in[4];
    const float* T      = (const float*)d_in[5];
    const float* LUT    = (const float*)d_in[6];
    float*       out    = (float*)d_out;

    static int attr_done = 0;   // host-side, idempotent (set on the pre-capture correctness call)
    if (!attr_done) {
        cudaFuncSetAttribute(k_masks, cudaFuncAttributeMaxDynamicSharedMemorySize, K1_SMEM);
        cudaFuncSetAttribute(k_cross, cudaFuncAttributeMaxDynamicSharedMemorySize, KX_SMEM);
        cudaFuncSetAttribute(k_main,  cudaFuncAttributeMaxDynamicSharedMemorySize, K4_SMEM);
        attr_done = 1;
    }

    k_masks <<<K1_BLK, K1_THR, K1_SMEM>>>(x, lenLUT, ipdLUT, S, T);
    k_tables<<<16, 1024>>>(H);
    k_cross <<<dim3(4, 4, 8), 256, KX_SMEM>>>();
    k_main  <<<K4_BLK, K4_THR, K4_SMEM>>>(LUT, out);
}

// round 10
// speedup vs baseline: 1.0172x; 1.0172x over previous
#include <cuda_runtime.h>

#define BATCH 131072
#define NCH 16
#define NK 15
#define NZ 256
#define NCOUT 10
#define MAXREG 128
#define VOCAB 1024
#define ZPAD 260                  // smem row stride (floats): conflict-free float4 phases

typedef unsigned long long u64;

// ---------------- scratch (device globals; no allocation) ----------------
__device__ unsigned       g_seen[NCH][1024];     // built by k_masks, read+zeroed by k_tables
__device__ unsigned char  g_rmap[NCH][32768];    // mask -> region id (observed entries valid this launch)
__device__ unsigned       g_maskw[BATCH * 8];    // packed masks: channel pair per u32
__device__ int            g_cnt[NCH];            // #distinct masks per channel (<=121)
__device__ float          g_zreg[NCH][MAXREG][NZ];       // per-region half z-row
__device__ unsigned char  g_cross[8][MAXREG][MAXREG];    // argmax index per (c8, rA, rB)

// ================= K1: per-element sign masks (f32x2 packed planes, fused observation) ===
#define K1_BLK 256
#define K1_THR 512
#define K1_SMEM (8192 + 8192 + 2880 + 65536)   // 84800 B

__global__ void __launch_bounds__(K1_THR, 2) k_masks(
    const int* __restrict__ x, const float* __restrict__ lenLUT,
    const float* __restrict__ ipdLUT, const float* __restrict__ S,
    const float* __restrict__ T)
{
    extern __shared__ char dyn[];
    float2*   sLen = (float2*)dyn;                       // 8 KB
    float2*   sIpd = (float2*)(dyn + 8192);              // 8 KB
    u64*      sS0  = (u64*)(dyn + 16384);                // 8 pairs x 15 k, packed (cA,cB)
    u64*      sS1  = sS0 + 120;
    u64*      sC   = sS1 + 120;                          // packed (-T-1e-4)
    unsigned* filt = (unsigned*)(dyn + 16384 + 2880);    // 64 KB block-local seen filter

    const int tid = threadIdx.x;
    for (int i = tid; i < VOCAB; i += K1_THR) {
        sLen[i] = ((const float2*)lenLUT)[i];
        sIpd[i] = ((const float2*)ipdLUT)[i];
    }
    if (tid < 120) {                                     // pack per-pair plane constants
        int i = tid / NK, k = tid % NK;
        int cA = 2 * i, cB = 2 * i + 1;
        u64 s0 = ((u64)__float_as_uint(S[cB * 30 + k])      << 32) | __float_as_uint(S[cA * 30 + k]);
        u64 s1 = ((u64)__float_as_uint(S[cB * 30 + 15 + k]) << 32) | __float_as_uint(S[cA * 30 + 15 + k]);
        float cAv = -T[cA * NK + k] - 1e-4f;
        float cBv = -T[cB * NK + k] - 1e-4f;
        u64 cc = ((u64)__float_as_uint(cBv) << 32) | __float_as_uint(cAv);
        sS0[tid] = s0; sS1[tid] = s1; sC[tid] = cc;
    }
    for (int i = tid; i < NCH * 1024; i += K1_THR) filt[i] = 0u;
    __syncthreads();

    const int b = blockIdx.x * K1_THR + tid;             // exact cover: 256*512 = BATCH
    const int4* xp = (const int4*)x + (size_t)b * 8;

    unsigned words[8];
    #pragma unroll
    for (int i = 0; i < 8; i++) {
        int4   xv = __ldg(&xp[i]);
        float2 lA = sLen[xv.x], pA = sIpd[xv.y];
        float2 lB = sLen[xv.z], pB = sIpd[xv.w];
        float e0A = lA.x + pA.x, e1A = lA.y + pA.y;
        float e0B = lB.x + pB.x, e1B = lB.y + pB.y;
        u64 e0p, e1p;
        asm("mov.b64 %0, {%1, %2};" : "=l"(e0p) : "f"(e0A), "f"(e0B));
        asm("mov.b64 %0, {%1, %2};" : "=l"(e1p) : "f"(e1A), "f"(e1B));
        unsigned pair = 0;
        #pragma unroll
        for (int k = 0; k < NK; k++) {
            u64 t2, y2;
            asm("fma.rn.f32x2 %0, %1, %2, %3;" : "=l"(t2) : "l"(e0p), "l"(sS0[i * NK + k]), "l"(sC[i * NK + k]));
            asm("fma.rn.f32x2 %0, %1, %2, %3;" : "=l"(y2) : "l"(e1p), "l"(sS1[i * NK + k]), "l"(t2));
            unsigned lo = (unsigned)y2;
            unsigned hi = (unsigned)(y2 >> 32);
            pair |= ((lo >> 31) << k) | ((hi >> 31) << (16 + k));   // bit set <=> y<0
        }
        words[i] = pair;
    }

    uint4* mp = (uint4*)&g_maskw[(size_t)b * 8];
    mp[0] = make_uint4(words[0], words[1], words[2], words[3]);
    mp[1] = make_uint4(words[4], words[5], words[6], words[7]);

    // seen-set update pass (block filter -> rare global atomic)
    #pragma unroll
    for (int i = 0; i < 8; i++) {
        #pragma unroll
        for (int h = 0; h < 2; h++) {
            unsigned m = (words[i] >> (16 * h)) & 0xffffu;
            int c = 2 * i + h;
            unsigned word = c * 1024 + (m >> 5), bit = 1u << (m & 31);
            if (!(filt[word] & bit)) {
                unsigned old = atomicOr(&filt[word], bit);
                if (!(old & bit)) atomicOr(&g_seen[c][m >> 5], bit);
            }
        }
    }
}

// ================= K2: dedup + global region map + self-clean + zreg =================
__global__ void __launch_bounds__(1024) k_tables(const float* __restrict__ H) {  // <<<16, 1024>>>
    const int c = blockIdx.x, tid = threadIdx.x;
    __shared__ int            sc[256];
    __shared__ unsigned short sMask[MAXREG];
    __shared__ float          sH[NK][NZ];
    __shared__ int            s_cnt;

    unsigned w[4]; int pc = 0;
    if (tid < 256) {
        #pragma unroll
        for (int j = 0; j < 4; j++) {
            w[j] = g_seen[c][tid * 4 + j];
            g_seen[c][tid * 4 + j] = 0u;               // self-clean for next launch
            pc += __popc(w[j]);
        }
        sc[tid] = pc;
    }
    const int base = (c & 1) * NK;                     // even ch -> H rows 0..14, odd -> 15..29
    for (int i = tid; i < NK * NZ; i += 1024)
        sH[i >> 8][i & 255] = H[(base + (i >> 8)) * NZ + (i & 255)];
    __syncthreads();
    for (int off = 1; off < 256; off <<= 1) {          // Hillis-Steele inclusive scan (256 lanes)
        int v = 0;
        if (tid < 256 && tid >= off) v = sc[tid - off];
        __syncthreads();
        if (tid < 256) sc[tid] += v;
        __syncthreads();
    }
    if (tid < 256) {
        int id = sc[tid] - pc;                         // exclusive prefix (ascending-mask order)
        if (tid == 255) { g_cnt[c] = min(sc[255], MAXREG); s_cnt = min(sc[255], MAXREG); }
        #pragma unroll
        for (int j = 0; j < 4; j++) {
            const int word = tid * 4 + j;
            unsigned ww = w[j];
            const unsigned mb = (unsigned)word << 5;
            while (ww) {
                int bb = __ffs(ww) - 1; ww &= ww - 1;
                if (id < MAXREG) {
                    unsigned short mask = (unsigned short)(mb | (unsigned)bb);
                    g_rmap[c][mask] = (unsigned char)id;   // global mask -> region id
                    sMask[id] = mask;
                }
                id++;
            }
        }
    }
    __syncthreads();

    const int cnt = s_cnt;
    const int col = tid & 255, grp = tid >> 8;         // 4-way row parallelism
    for (int r = grp; r < cnt; r += 4) {
        unsigned m = sMask[r];
        float acc = 0.f;
        #pragma unroll
        for (int d = 0; d < NK; d++) {
            float hv = sH[d][col];
            acc += ((m >> d) & 1) ? -hv : hv;
        }
        g_zreg[c][r][col] = acc;
    }
}

// ================= K3: argmax table — 2-pass FMNMX/IMNMX, no pred chains, no shuffles ====
// grid = dim3(4 rA-tiles, 4 rB-tiles, 8 pairs), block = 1024 (one thread per (rA,rB) pair).
// lane <-> rA (zA tile in smem, ZPAD stride -> conflict-free float4 phases);
// warp <-> rB (zB row broadcast __ldg). Pass1: exact fp32 max via fmaxf trees.
// Pass2: recompute identical a+b, take min k with v == best (SEL + IMNMX trees).
// First-k-wins over exact-equal maxima == jnp.argmax semantics.
#define KX_SMEM (32 * ZPAD * 4)   // 33280 B

__global__ void __launch_bounds__(1024, 2) k_cross() {
    const int rAt = blockIdx.x, rBt = blockIdx.y, c8 = blockIdx.z;
    const int cA = 2 * c8, cB = cA + 1;
    const int nA = g_cnt[cA], nB = g_cnt[cB];
    const int rA0 = rAt * 32, rB0 = rBt * 32;
    if (rA0 >= nA || rB0 >= nB) return;                 // uniform per block

    extern __shared__ float zA[];                       // [32][ZPAD]
    const int tid = threadIdx.x;
    for (int i = tid; i < 32 * NZ; i += 1024) {         // stage zA tile
        int row = i >> 8, col = i & 255;
        zA[row * ZPAD + col] = g_zreg[cA][rA0 + row][col];
    }
    __syncthreads();

    const int lane = tid & 31;                          // rA within tile
    const int wrp  = tid >> 5;                          // rB within tile
    const int rA = rA0 + lane, rB = rB0 + wrp;
    if (rB >= nB) return;                               // warp-uniform exit
    const bool aLive = (rA < nA);
    const float4* zAl = (const float4*)&zA[lane * ZPAD];
    const float4* zb  = (const float4*)&g_zreg[cB][rB][0];

    // ---- pass 1: exact max value (4 independent FMNMX accumulators) ----
    const float NEG = __int_as_float(0xff800000);       // -inf
    float mx0 = NEG, mx1 = NEG, mx2 = NEG, mx3 = NEG;
    #pragma unroll 8
    for (int k4 = 0; k4 < 64; k4++) {
        float4 a = zAl[k4];
        float4 b = __ldg(&zb[k4]);
        mx0 = fmaxf(mx0, a.x + b.x);
        mx1 = fmaxf(mx1, a.y + b.y);
        mx2 = fmaxf(mx2, a.z + b.z);
        mx3 = fmaxf(mx3, a.w + b.w);
    }
    const float best = fmaxf(fmaxf(mx0, mx1), fmaxf(mx2, mx3));

    // ---- pass 2: first k with v == best (SEL + IMNMX, all lat-4, tree-parallel) ----
    int i0 = 1023, i1 = 1023, i2 = 1023, i3 = 1023;
    #pragma unroll 8
    for (int k4 = 0; k4 < 64; k4++) {
        float4 a = zAl[k4];
        float4 b = __ldg(&zb[k4]);
        const int kb = k4 * 4;
        i0 = min(i0, (a.x + b.x == best) ? kb     : 1023);
        i1 = min(i1, (a.y + b.y == best) ? kb + 1 : 1023);
        i2 = min(i2, (a.z + b.z == best) ? kb + 2 : 1023);
        i3 = min(i3, (a.w + b.w == best) ? kb + 3 : 1023);
    }
    const int bk = min(min(i0, i1), min(i2, i3));
    if (aLive) g_cross[c8][rA][rB] = (unsigned char)bk;
}

// ================= K4: gather (L2 rmap/cross + smem LUT) + log_softmax =================
#define K4_BLK 256
#define K4_THR 512
#define LUTPAD 12
#define K4_SMEM (8 * 256 * LUTPAD * 4)   // 98304 B -> 2 blocks/SM

__global__ void __launch_bounds__(K4_THR, 2) k_main(
    const float* __restrict__ LUT, float* __restrict__ out)
{
    extern __shared__ char dyn[];
    float* slut = (float*)dyn;

    const int tid = threadIdx.x;
    for (int row = tid; row < 8 * 256; row += K4_THR) {
        #pragma unroll
        for (int j = 0; j < LUTPAD; j++)
            slut[row * LUTPAD + j] = (j < NCOUT) ? LUT[row * NCOUT + j] : 0.f;
    }
    __syncthreads();

    const int b = blockIdx.x * K4_THR + tid;             // exact cover: 256*512 = BATCH
    const uint4* mp = (const uint4*)&g_maskw[(size_t)b * 8];
    uint4 m0 = mp[0], m1 = mp[1];
    unsigned mw[8] = {m0.x, m0.y, m0.z, m0.w, m1.x, m1.y, m1.z, m1.w};

    int r[NCH];
    #pragma unroll
    for (int i = 0; i < 8; i++) {                        // 16 independent L2 u8 loads
        r[2 * i]     = __ldg(&g_rmap[2 * i][mw[i] & 0xffffu]);
        r[2 * i + 1] = __ldg(&g_rmap[2 * i + 1][mw[i] >> 16]);
    }

    int idx[8];
    #pragma unroll
    for (int c8 = 0; c8 < 8; c8++)                       // 8 independent L2 u8 loads
        idx[c8] = __ldg(&g_cross[c8][r[2 * c8]][r[2 * c8 + 1]]);

    float4 a0 = make_float4(0.f, 0.f, 0.f, 0.f), a1 = a0, a2 = a0;
    #pragma unroll
    for (int c8 = 0; c8 < 8; c8++) {
        const float4* p = (const float4*)&slut[(c8 * 256 + idx[c8]) * LUTPAD];
        float4 v0 = p[0], v1 = p[1], v2 = p[2];
        a0.x += v0.x; a0.y += v0.y; a0.z += v0.z; a0.w += v0.w;
        a1.x += v1.x; a1.y += v1.y; a1.z += v1.z; a1.w += v1.w;
        a2.x += v2.x; a2.y += v2.y;                      // lanes 10,11 are pad
    }
    float acc[NCOUT] = {a0.x, a0.y, a0.z, a0.w, a1.x, a1.y, a1.z, a1.w, a2.x, a2.y};

    float mx = acc[0];
    #pragma unroll
    for (int j = 1; j < NCOUT; j++) mx = fmaxf(mx, acc[j]);
    float s = 0.f;
    #pragma unroll
    for (int j = 0; j < NCOUT; j++) s += __expf(acc[j] - mx);
    float lg = __logf(s);

    float2* op = (float2*)(out + (size_t)b * NCOUT);
    #pragma unroll
    for (int j = 0; j < 5; j++)
        op[j] = make_float2((acc[2 * j] - mx) - lg, (acc[2 * j + 1] - mx) - lg);
}

// ---------------- launch ----------------
extern "C" void kernel_launch(void* const* d_in, const int* in_sizes, int n_in,
                              void* d_out, int out_size) {
    const int*   x      = (const int*)d_in[0];
    const float* lenLUT = (const float*)d_in[1];
    const float* ipdLUT = (const float*)d_in[2];
    const float* S      = (const float*)d_in[3];
    const float* H      = (const float*)d_in[4];
    const float* T      = (const float*)d_in[5];
    const float* LUT    = (const float*)d_in[6];
    float*       out    = (float*)d_out;

    static int attr_done = 0;   // host-side, idempotent (set on the pre-capture correctness call)
    if (!attr_done) {
        cudaFuncSetAttribute(k_masks, cudaFuncAttributeMaxDynamicSharedMemorySize, K1_SMEM);
        cudaFuncSetAttribute(k_cross, cudaFuncAttributeMaxDynamicSharedMemorySize, KX_SMEM);
        cudaFuncSetAttribute(k_main,  cudaFuncAttributeMaxDynamicSharedMemorySize, K4_SMEM);
        attr_done = 1;
    }

    k_masks <<<K1_BLK, K1_THR, K1_SMEM>>>(x, lenLUT, ipdLUT, S, T);
    k_tables<<<16, 1024>>>(H);
    k_cross <<<dim3(4, 4, 8), 1024, KX_SMEM>>>();
    k_main  <<<K4_BLK, K4_THR, K4_SMEM>>>(LUT, out);
}

// round 11
// speedup vs baseline: 1.0955x; 1.0770x over previous
#include <cuda_runtime.h>

#define BATCH 131072
#define NCH 16
#define NK 15
#define NZ 256
#define NCOUT 10
#define MAXREG 128
#define VOCAB 1024

typedef unsigned long long u64;

// ---------------- scratch (device globals; no allocation) ----------------
__device__ unsigned       g_seen[NCH][1024];     // built by k_masks, read+zeroed by k_tables
__device__ unsigned char  g_rmap[NCH][32768];    // mask -> region id (observed entries valid this launch)
__device__ unsigned       g_maskw[BATCH * 8];    // packed masks: channel pair per u32
__device__ int            g_cnt[NCH];            // #distinct masks per channel (<=121)
__device__ float          g_zreg[NCH][MAXREG][NZ];       // per-region half z-row
__device__ unsigned char  g_cross[8][MAXREG][MAXREG];    // argmax index per (c8, rA, rB)

// ================= K1: sign masks — 2 elements/thread, constants amortized ==============
// Thread t of block g handles b0 = g*256+t and b1 = b0+65536 (both coalesced).
// Per (i,k): one LDS.128 (packed S0,S1) + one LDS.64 (packed C) feeds BOTH elements
// -> uniform-constant LDS ops per element drop 3x vs one-element-per-thread.
#define K1_BLK 256
#define K1_THR 256
#define K1_SMEM (8192 + 8192 + 1920 + 960 + 65536)   // 84800 B -> 2 blocks/SM

__global__ void __launch_bounds__(K1_THR, 2) k_masks(
    const int* __restrict__ x, const float* __restrict__ lenLUT,
    const float* __restrict__ ipdLUT, const float* __restrict__ S,
    const float* __restrict__ T)
{
    extern __shared__ char dyn[];
    float2*     sLen = (float2*)dyn;                     // 8 KB
    float2*     sIpd = (float2*)(dyn + 8192);            // 8 KB
    ulonglong2* sSP  = (ulonglong2*)(dyn + 16384);       // 120 x {S0p, S1p}  (1920 B)
    u64*        sC   = (u64*)(dyn + 16384 + 1920);       // 120 x packed (-T-1e-4) (960 B)
    unsigned*   filt = (unsigned*)(dyn + 16384 + 2880);  // 64 KB block-local seen filter

    const int tid = threadIdx.x;
    for (int i = tid; i < VOCAB; i += K1_THR) {
        sLen[i] = ((const float2*)lenLUT)[i];
        sIpd[i] = ((const float2*)ipdLUT)[i];
    }
    if (tid < 120) {                                     // pack per-pair plane constants
        int i = tid / NK, k = tid % NK;
        int cA = 2 * i, cB = 2 * i + 1;
        u64 s0 = ((u64)__float_as_uint(S[cB * 30 + k])      << 32) | __float_as_uint(S[cA * 30 + k]);
        u64 s1 = ((u64)__float_as_uint(S[cB * 30 + 15 + k]) << 32) | __float_as_uint(S[cA * 30 + 15 + k]);
        float cAv = -T[cA * NK + k] - 1e-4f;
        float cBv = -T[cB * NK + k] - 1e-4f;
        sSP[tid] = make_ulonglong2(s0, s1);
        sC[tid]  = ((u64)__float_as_uint(cBv) << 32) | __float_as_uint(cAv);
    }
    for (int i = tid; i < NCH * 1024; i += K1_THR) filt[i] = 0u;
    __syncthreads();

    const int b0 = blockIdx.x * K1_THR + tid;            // 256*256 = 65536 threads, 2 elems each
    const int b1 = b0 + 65536;
    const int4* xp0 = (const int4*)x + (size_t)b0 * 8;
    const int4* xp1 = (const int4*)x + (size_t)b1 * 8;

    unsigned w0[8], w1[8];
    #pragma unroll
    for (int i = 0; i < 8; i++) {
        int4 xv0 = __ldg(&xp0[i]);
        int4 xv1 = __ldg(&xp1[i]);

        float2 lA0 = sLen[xv0.x], pA0 = sIpd[xv0.y];
        float2 lB0 = sLen[xv0.z], pB0 = sIpd[xv0.w];
        float2 lA1 = sLen[xv1.x], pA1 = sIpd[xv1.y];
        float2 lB1 = sLen[xv1.z], pB1 = sIpd[xv1.w];

        u64 e0p0, e1p0, e0p1, e1p1;
        {
            float a = lA0.x + pA0.x, b = lB0.x + pB0.x;
            asm("mov.b64 %0, {%1, %2};" : "=l"(e0p0) : "f"(a), "f"(b));
            float c = lA0.y + pA0.y, d = lB0.y + pB0.y;
            asm("mov.b64 %0, {%1, %2};" : "=l"(e1p0) : "f"(c), "f"(d));
            float e = lA1.x + pA1.x, f = lB1.x + pB1.x;
            asm("mov.b64 %0, {%1, %2};" : "=l"(e0p1) : "f"(e), "f"(f));
            float g = lA1.y + pA1.y, h = lB1.y + pB1.y;
            asm("mov.b64 %0, {%1, %2};" : "=l"(e1p1) : "f"(g), "f"(h));
        }

        unsigned pair0 = 0, pair1 = 0;
        #pragma unroll
        for (int k = 0; k < NK; k++) {
            ulonglong2 sp = sSP[i * NK + k];             // LDS.128: S0p, S1p
            u64        cc = sC[i * NK + k];              // LDS.64
            u64 t0, y0, t1, y1;
            asm("fma.rn.f32x2 %0, %1, %2, %3;" : "=l"(t0) : "l"(e0p0), "l"(sp.x), "l"(cc));
            asm("fma.rn.f32x2 %0, %1, %2, %3;" : "=l"(t1) : "l"(e0p1), "l"(sp.x), "l"(cc));
            asm("fma.rn.f32x2 %0, %1, %2, %3;" : "=l"(y0) : "l"(e1p0), "l"(sp.y), "l"(t0));
            asm("fma.rn.f32x2 %0, %1, %2, %3;" : "=l"(y1) : "l"(e1p1), "l"(sp.y), "l"(t1));
            unsigned lo0 = (unsigned)y0, hi0 = (unsigned)(y0 >> 32);
            unsigned lo1 = (unsigned)y1, hi1 = (unsigned)(y1 >> 32);
            pair0 |= ((lo0 >> 31) << k) | ((hi0 >> 31) << (16 + k));  // bit set <=> y<0
            pair1 |= ((lo1 >> 31) << k) | ((hi1 >> 31) << (16 + k));
        }
        w0[i] = pair0;
        w1[i] = pair1;
    }

    {
        uint4* mp0 = (uint4*)&g_maskw[(size_t)b0 * 8];
        mp0[0] = make_uint4(w0[0], w0[1], w0[2], w0[3]);
        mp0[1] = make_uint4(w0[4], w0[5], w0[6], w0[7]);
        uint4* mp1 = (uint4*)&g_maskw[(size_t)b1 * 8];
        mp1[0] = make_uint4(w1[0], w1[1], w1[2], w1[3]);
        mp1[1] = make_uint4(w1[4], w1[5], w1[6], w1[7]);
    }

    // seen-set update for both elements (block filter -> rare global atomic)
    #pragma unroll
    for (int i = 0; i < 8; i++) {
        #pragma unroll
        for (int h = 0; h < 2; h++) {
            unsigned m0 = (w0[i] >> (16 * h)) & 0xffffu;
            unsigned m1 = (w1[i] >> (16 * h)) & 0xffffu;
            int c = 2 * i + h;
            unsigned wd0 = c * 1024 + (m0 >> 5), bt0 = 1u << (m0 & 31);
            if (!(filt[wd0] & bt0)) {
                unsigned old = atomicOr(&filt[wd0], bt0);
                if (!(old & bt0)) atomicOr(&g_seen[c][m0 >> 5], bt0);
            }
            unsigned wd1 = c * 1024 + (m1 >> 5), bt1 = 1u << (m1 & 31);
            if (!(filt[wd1] & bt1)) {
                unsigned old = atomicOr(&filt[wd1], bt1);
                if (!(old & bt1)) atomicOr(&g_seen[c][m1 >> 5], bt1);
            }
        }
    }
}

// ================= K2: dedup + global region map + self-clean + zreg =================
__global__ void __launch_bounds__(1024) k_tables(const float* __restrict__ H) {  // <<<16, 1024>>>
    const int c = blockIdx.x, tid = threadIdx.x;
    __shared__ int            sc[256];
    __shared__ unsigned short sMask[MAXREG];
    __shared__ float          sH[NK][NZ];
    __shared__ int            s_cnt;

    unsigned w[4]; int pc = 0;
    if (tid < 256) {
        #pragma unroll
        for (int j = 0; j < 4; j++) {
            w[j] = g_seen[c][tid * 4 + j];
            g_seen[c][tid * 4 + j] = 0u;               // self-clean for next launch
            pc += __popc(w[j]);
        }
        sc[tid] = pc;
    }
    const int base = (c & 1) * NK;                     // even ch -> H rows 0..14, odd -> 15..29
    for (int i = tid; i < NK * NZ; i += 1024)
        sH[i >> 8][i & 255] = H[(base + (i >> 8)) * NZ + (i & 255)];
    __syncthreads();
    for (int off = 1; off < 256; off <<= 1) {          // Hillis-Steele inclusive scan (256 lanes)
        int v = 0;
        if (tid < 256 && tid >= off) v = sc[tid - off];
        __syncthreads();
        if (tid < 256) sc[tid] += v;
        __syncthreads();
    }
    if (tid < 256) {
        int id = sc[tid] - pc;                         // exclusive prefix (ascending-mask order)
        if (tid == 255) { g_cnt[c] = min(sc[255], MAXREG); s_cnt = min(sc[255], MAXREG); }
        #pragma unroll
        for (int j = 0; j < 4; j++) {
            const int word = tid * 4 + j;
            unsigned ww = w[j];
            const unsigned mb = (unsigned)word << 5;
            while (ww) {
                int bb = __ffs(ww) - 1; ww &= ww - 1;
                if (id < MAXREG) {
                    unsigned short mask = (unsigned short)(mb | (unsigned)bb);
                    g_rmap[c][mask] = (unsigned char)id;   // global mask -> region id
                    sMask[id] = mask;
                }
                id++;
            }
        }
    }
    __syncthreads();

    const int cnt = s_cnt;
    const int col = tid & 255, grp = tid >> 8;         // 4-way row parallelism
    for (int r = grp; r < cnt; r += 4) {
        unsigned m = sMask[r];
        float acc = 0.f;
        #pragma unroll
        for (int d = 0; d < NK; d++) {
            float hv = sH[d][col];
            acc += ((m >> d) & 1) ? -hv : hv;
        }
        g_zreg[c][r][col] = acc;
    }
}

// ================= K3: argmax table, rA tiled x4 (R6 shuffle version) =================
__global__ void k_cross() {   // <<<dim3(32, 8), 256>>>
    const int c8 = blockIdx.y, rAt = blockIdx.x;
    const int cA = 2 * c8, cB = cA + 1;
    const int nA = g_cnt[cA], nB = g_cnt[cB];
    const int rA0 = rAt * 4;
    if (rA0 >= nA) return;
    const int na = min(4, nA - rA0);
    __shared__ float zA[4][NZ];
    for (int i = threadIdx.x; i < 4 * NZ; i += 256) {
        int rr = i >> 8, k = i & 255;
        zA[rr][k] = (rr < na) ? g_zreg[cA][rA0 + rr][k] : 0.f;
    }
    __syncthreads();
    const int warp = threadIdx.x >> 5, lane = threadIdx.x & 31;
    for (int rB = warp; rB < nB; rB += 8) {
        const float* zb = &g_zreg[cB][rB][0];
        float zl[8];
        #pragma unroll
        for (int j = 0; j < 8; j++) zl[j] = zb[j * 32 + lane];
        #pragma unroll
        for (int i2 = 0; i2 < 4; i2++) {
            float best = __int_as_float(0xff800000);  // -inf
            int   bk = 0;
            #pragma unroll
            for (int j = 0; j < 8; j++) {
                int k = j * 32 + lane;                // ascending per lane
                float v = zA[i2][k] + zl[j];
                if (v > best) { best = v; bk = k; }
            }
            #pragma unroll
            for (int off = 16; off; off >>= 1) {      // first-index-wins warp argmax
                float ov = __shfl_down_sync(0xffffffffu, best, off);
                int   ok = __shfl_down_sync(0xffffffffu, bk, off);
                if (ov > best || (ov == best && ok < bk)) { best = ov; bk = ok; }
            }
            if (lane == 0 && i2 < na) g_cross[c8][rA0 + i2][rB] = (unsigned char)bk;
        }
    }
}

// ================= K4: gather (L2 rmap/cross + smem LUT) + log_softmax =================
#define K4_BLK 256
#define K4_THR 512
#define LUTPAD 12
#define K4_SMEM (8 * 256 * LUTPAD * 4)   // 98304 B -> 2 blocks/SM

__global__ void __launch_bounds__(K4_THR, 2) k_main(
    const float* __restrict__ LUT, float* __restrict__ out)
{
    extern __shared__ char dyn[];
    float* slut = (float*)dyn;

    const int tid = threadIdx.x;
    for (int row = tid; row < 8 * 256; row += K4_THR) {
        #pragma unroll
        for (int j = 0; j < LUTPAD; j++)
            slut[row * LUTPAD + j] = (j < NCOUT) ? LUT[row * NCOUT + j] : 0.f;
    }
    __syncthreads();

    const int b = blockIdx.x * K4_THR + tid;             // exact cover: 256*512 = BATCH
    const uint4* mp = (const uint4*)&g_maskw[(size_t)b * 8];
    uint4 m0 = mp[0], m1 = mp[1];
    unsigned mw[8] = {m0.x, m0.y, m0.z, m0.w, m1.x, m1.y, m1.z, m1.w};

    int r[NCH];
    #pragma unroll
    for (int i = 0; i < 8; i++) {                        // 16 independent L2 u8 loads
        r[2 * i]     = __ldg(&g_rmap[2 * i][mw[i] & 0xffffu]);
        r[2 * i + 1] = __ldg(&g_rmap[2 * i + 1][mw[i] >> 16]);
    }

    int idx[8];
    #pragma unroll
    for (int c8 = 0; c8 < 8; c8++)                       // 8 independent L2 u8 loads
        idx[c8] = __ldg(&g_cross[c8][r[2 * c8]][r[2 * c8 + 1]]);

    float4 a0 = make_float4(0.f, 0.f, 0.f, 0.f), a1 = a0, a2 = a0;
    #pragma unroll
    for (int c8 = 0; c8 < 8; c8++) {
        const float4* p = (const float4*)&slut[(c8 * 256 + idx[c8]) * LUTPAD];
        float4 v0 = p[0], v1 = p[1], v2 = p[2];
        a0.x += v0.x; a0.y += v0.y; a0.z += v0.z; a0.w += v0.w;
        a1.x += v1.x; a1.y += v1.y; a1.z += v1.z; a1.w += v1.w;
        a2.x += v2.x; a2.y += v2.y;                      // lanes 10,11 are pad
    }
    float acc[NCOUT] = {a0.x, a0.y, a0.z, a0.w, a1.x, a1.y, a1.z, a1.w, a2.x, a2.y};

    float mx = acc[0];
    #pragma unroll
    for (int j = 1; j < NCOUT; j++) mx = fmaxf(mx, acc[j]);
    float s = 0.f;
    #pragma unroll
    for (int j = 0; j < NCOUT; j++) s += __expf(acc[j] - mx);
    float lg = __logf(s);

    float2* op = (float2*)(out + (size_t)b * NCOUT);
    #pragma unroll
    for (int j = 0; j < 5; j++)
        op[j] = make_float2((acc[2 * j] - mx) - lg, (acc[2 * j + 1] - mx) - lg);
}

// ---------------- launch ----------------
extern "C" void kernel_launch(void* const* d_in, const int* in_sizes, int n_in,
                              void* d_out, int out_size) {
    const int*   x      = (const int*)d_in[0];
    const float* lenLUT = (const float*)d_in[1];
    const float* ipdLUT = (const float*)d_in[2];
    const float* S      = (const float*)d_in[3];
    const float* H      = (const float*)d_in[4];
    const float* T      = (const float*)d_in[5];
    const float* LUT    = (const float*)d_in[6];
    float*       out    = (float*)d_out;

    static int attr_done = 0;   // host-side, idempotent (set on the pre-capture correctness call)
    if (!attr_done) {
        cudaFuncSetAttribute(k_masks, cudaFuncAttributeMaxDynamicSharedMemorySize, K1_SMEM);
        cudaFuncSetAttribute(k_main,  cudaFuncAttributeMaxDynamicSharedMemorySize, K4_SMEM);
        attr_done = 1;
    }

    k_masks <<<K1_BLK, K1_THR, K1_SMEM>>>(x, lenLUT, ipdLUT, S, T);
    k_tables<<<16, 1024>>>(H);
    k_cross <<<dim3(32, 8), 256>>>();
    k_main  <<<K4_BLK, K4_THR, K4_SMEM>>>(LUT, out);
}